// round 14
// baseline (speedup 1.0000x reference)
#include <cuda_runtime.h>
#include <cuda_bf16.h>
#include <cstdint>

#define IMG   128
#define CDIM  256
#define HDS   8
#define HD    32
#define NELEM 33554432   // 131072 * 256

// Scratch (allocation-free rule: device globals)
__device__ float          g_v[NELEM];                 // v buffer fp32
__device__ __nv_bfloat16  g_oh[NELEM], g_ol[NELEM];   // agg output split
__device__ __nv_bfloat16  g_wvh[65536], g_wvl[65536];
__device__ __nv_bfloat16  g_wph[65536], g_wpl[65536];

// ---------------------------------------------------------------------------
// helpers
// ---------------------------------------------------------------------------
__device__ __forceinline__ uint32_t smem_u32(const void* p) {
    uint32_t a;
    asm("{ .reg .u64 t; cvta.to.shared.u64 t, %1; cvt.u32.u64 %0, t; }"
        : "=r"(a) : "l"(p));
    return a;
}
__device__ __forceinline__ void cp16(uint32_t saddr, const void* g) {
    asm volatile("cp.async.cg.shared.global [%0], [%1], 16;"
                 :: "r"(saddr), "l"(g));
}
__device__ __forceinline__ void cp4(uint32_t saddr, const void* g) {
    asm volatile("cp.async.ca.shared.global [%0], [%1], 4;"
                 :: "r"(saddr), "l"(g));
}
__device__ __forceinline__ void ldm_x4(uint32_t* d, uint32_t a) {
    asm volatile("ldmatrix.sync.aligned.m8n8.x4.shared.b16 {%0,%1,%2,%3}, [%4];"
                 : "=r"(d[0]), "=r"(d[1]), "=r"(d[2]), "=r"(d[3]) : "r"(a));
}
__device__ __forceinline__ void mma16816(float* c, const uint32_t* a, const uint32_t* b) {
    asm volatile("mma.sync.aligned.m16n8k16.row.col.f32.bf16.bf16.f32 "
                 "{%0,%1,%2,%3}, {%4,%5,%6,%7}, {%8,%9}, {%0,%1,%2,%3};"
                 : "+f"(c[0]), "+f"(c[1]), "+f"(c[2]), "+f"(c[3])
                 : "r"(a[0]), "r"(a[1]), "r"(a[2]), "r"(a[3]),
                   "r"(b[0]), "r"(b[1]));
}
__device__ __forceinline__ uint32_t pack_bf2(float x, float y) {
    __nv_bfloat162 t = __floats2bfloat162_rn(x, y);
    return *reinterpret_cast<uint32_t*>(&t);
}
__device__ __forceinline__ uint32_t pack_hi2(float x, float y) {
    __nv_bfloat16 hx = __float2bfloat16(x), hy = __float2bfloat16(y);
    return ((uint32_t)__bfloat16_as_ushort(hy) << 16) | __bfloat16_as_ushort(hx);
}
__device__ __forceinline__ uint32_t pack_lo2(float x, float y) {
    __nv_bfloat16 hx = __float2bfloat16(x), hy = __float2bfloat16(y);
    return pack_bf2(x - __bfloat162float(hx), y - __bfloat162float(hy));
}

// ---------------------------------------------------------------------------
// W split: fp32 -> bf16 hi/lo (both weight matrices)
// ---------------------------------------------------------------------------
__global__ void split_w_kernel(const float* __restrict__ W1,
                               __nv_bfloat16* __restrict__ h1, __nv_bfloat16* __restrict__ l1,
                               const float* __restrict__ W2,
                               __nv_bfloat16* __restrict__ h2, __nv_bfloat16* __restrict__ l2)
{
    int i = blockIdx.x * 256 + threadIdx.x;
    float a = W1[i];
    __nv_bfloat16 ha = __float2bfloat16(a);
    h1[i] = ha;
    l1[i] = __float2bfloat16(a - __bfloat162float(ha));
    float b = W2[i];
    __nv_bfloat16 hb = __float2bfloat16(b);
    h2[i] = hb;
    l2[i] = __float2bfloat16(b - __bfloat162float(hb));
}

// ---------------------------------------------------------------------------
// GEMM: CTA tile 128x64, 8 warps of 32x32, 3-stage cp.async, BK=32,
// XOR-swizzled 64B rows, LDSM-x4 dual-nt B fragments, 3 CTAs/SM.
// Stage layout: AH(8192) | AL(8192) | BH(4096) | BL(4096) = 24576 B.
// ---------------------------------------------------------------------------
#define NCHUNK 8
#define ROWB   64
#define MATB_A 8192
#define MATB_B 4096
#define STAGEB 24576
#define OFF_AH 0
#define OFF_AL 8192
#define OFF_BH 16384
#define OFF_BL 20480
#define GM_SMEM (3 * STAGEB)       // 73728

__device__ __forceinline__ uint32_t swz_off(int r, int c) {
    return (uint32_t)(r * ROWB) + (uint32_t)((c ^ ((r >> 1) & 3)) << 4);
}

struct GemmCtx {
    uint32_t sb;
    int tid, lane, bm, bn, m0, n0;
    int a_row, b4_row;
    uint32_t a_xor, b_xor;
    int a_seg, b_seg;
};

__device__ __forceinline__ GemmCtx gemm_ctx_init(uint32_t sb) {
    GemmCtx g;
    g.sb = sb;
    g.tid = threadIdx.x;
    const int wid = g.tid >> 5;
    g.lane = g.tid & 31;
    g.bm = blockIdx.x * 128; g.bn = blockIdx.y * 64;
    g.m0 = (wid & 3) * 32; g.n0 = (wid >> 2) * 32;
    g.a_row = g.lane & 15;
    g.b4_row = (g.lane & 7) + (g.lane >> 4) * 8;
    g.a_xor = (uint32_t)((g.a_row >> 1) & 3);
    g.b_xor = (uint32_t)(((g.lane & 7) >> 1) & 3);
    g.a_seg = (g.lane >> 4);
    g.b_seg = (g.lane >> 3) & 1;
    return g;
}

__device__ __forceinline__ void gemm_compute_chunk32(
    const GemmCtx& g, uint32_t stb, float acc[2][4][4])
{
#pragma unroll
    for (int k16 = 0; k16 < 2; k16++) {
        uint32_t AhF[2][4], AlF[2][4];
        const uint32_t a_segoff = (uint32_t)(((2 * k16 + g.a_seg) ^ g.a_xor) << 4);
        const uint32_t b_segoff = (uint32_t)(((2 * k16 + g.b_seg) ^ g.b_xor) << 4);
#pragma unroll
        for (int mt = 0; mt < 2; mt++) {
            const uint32_t aaddr = stb
                + (uint32_t)((g.m0 + mt * 16 + g.a_row) * ROWB) + a_segoff;
            ldm_x4(AhF[mt], aaddr + OFF_AH);
            ldm_x4(AlF[mt], aaddr + OFF_AL);
        }
#pragma unroll
        for (int np = 0; np < 2; np++) {
            const uint32_t baddr = stb
                + (uint32_t)((g.n0 + np * 16 + g.b4_row) * ROWB) + b_segoff;
            uint32_t bh[4], bl[4];
            ldm_x4(bh, baddr + OFF_BH);
            ldm_x4(bl, baddr + OFF_BL);
            const int nt0 = 2 * np, nt1 = 2 * np + 1;
            mma16816(acc[0][nt0], AhF[0], bh + 0);
            mma16816(acc[1][nt0], AhF[1], bh + 0);
            mma16816(acc[0][nt1], AhF[0], bh + 2);
            mma16816(acc[1][nt1], AhF[1], bh + 2);
            mma16816(acc[0][nt0], AlF[0], bh + 0);
            mma16816(acc[1][nt0], AlF[1], bh + 0);
            mma16816(acc[0][nt1], AlF[0], bh + 2);
            mma16816(acc[1][nt1], AlF[1], bh + 2);
            mma16816(acc[0][nt0], AhF[0], bl + 0);
            mma16816(acc[1][nt0], AhF[1], bl + 0);
            mma16816(acc[0][nt1], AhF[0], bl + 2);
            mma16816(acc[1][nt1], AhF[1], bl + 2);
        }
    }
}

__device__ __forceinline__ void gemm_epilogue(
    const GemmCtx& g, float acc[2][4][4],
    const float* __restrict__ bias, float* __restrict__ C)
{
#pragma unroll
    for (int mt = 0; mt < 2; mt++) {
        const int row = g.bm + g.m0 + mt * 16 + (g.lane >> 2);
#pragma unroll
        for (int nt = 0; nt < 4; nt++) {
            const int col = g.bn + g.n0 + nt * 8 + 2 * (g.lane & 3);
            const float b0 = __ldg(bias + col), b1 = __ldg(bias + col + 1);
            float2 v0, v1;
            v0.x = acc[mt][nt][0] + b0; v0.y = acc[mt][nt][1] + b1;
            v1.x = acc[mt][nt][2] + b0; v1.y = acc[mt][nt][3] + b1;
            *reinterpret_cast<float2*>(C + (size_t)row * 256 + col) = v0;
            *reinterpret_cast<float2*>(C + (size_t)(row + 8) * 256 + col) = v1;
        }
    }
}

// ---------------------------------------------------------------------------
// GEMM (A bf16 hi/lo)
// ---------------------------------------------------------------------------
__global__ void __launch_bounds__(256, 3)
gemm_bf16a_kernel(const __nv_bfloat16* __restrict__ Ah_g,
                  const __nv_bfloat16* __restrict__ Al_g,
                  const __nv_bfloat16* __restrict__ Bh_g,
                  const __nv_bfloat16* __restrict__ Bl_g,
                  const float* __restrict__ bias,
                  float* __restrict__ C)
{
    extern __shared__ char sm[];
    const uint32_t sb = smem_u32(sm);
    GemmCtx g = gemm_ctx_init(sb);
    const int tid = g.tid;

    auto load_chunk = [&](int kc, int st) {
        // A: 512 granules -> 2 tasks/thread
#pragma unroll
        for (int s = 0; s < 2; s++) {
            const int idx = tid + s * 256;
            const int r = idx >> 2, c = idx & 3;
            const uint32_t so = (uint32_t)(st * STAGEB) + swz_off(r, c);
            const size_t goA = (size_t)(g.bm + r) * 256 + kc * 32 + c * 8;
            cp16(sb + so + OFF_AH, Ah_g + goA);
            cp16(sb + so + OFF_AL, Al_g + goA);
        }
        // B: 256 granules -> 1 task/thread
        {
            const int r = tid >> 2, c = tid & 3;
            const uint32_t so = (uint32_t)(st * STAGEB) + swz_off(r, c);
            const size_t goB = (size_t)(g.bn + r) * 256 + kc * 32 + c * 8;
            cp16(sb + so + OFF_BH, Bh_g + goB);
            cp16(sb + so + OFF_BL, Bl_g + goB);
        }
    };

    float acc[2][4][4];
#pragma unroll
    for (int mt = 0; mt < 2; mt++)
#pragma unroll
        for (int nt = 0; nt < 4; nt++)
#pragma unroll
            for (int q = 0; q < 4; q++) acc[mt][nt][q] = 0.f;

    load_chunk(0, 0);
    asm volatile("cp.async.commit_group;" ::: "memory");
    load_chunk(1, 1);
    asm volatile("cp.async.commit_group;" ::: "memory");

    int sr = 0, sw = 2;
    for (int kc = 0; kc < NCHUNK; kc++) {
        asm volatile("cp.async.wait_group 1;" ::: "memory");
        __syncthreads();
        if (kc + 2 < NCHUNK) {
            load_chunk(kc + 2, sw);
            if (++sw == 3) sw = 0;
        }
        asm volatile("cp.async.commit_group;" ::: "memory");
        gemm_compute_chunk32(g, sb + (uint32_t)(sr * STAGEB), acc);
        if (++sr == 3) sr = 0;
    }
    gemm_epilogue(g, acc, bias, C);
}

// ---------------------------------------------------------------------------
// GEMM (A fp32): A register-staged + converted inline; B via cp.async.
// ---------------------------------------------------------------------------
__global__ void __launch_bounds__(256, 3)
gemm_f32a_kernel(const float* __restrict__ A_g,
                 const __nv_bfloat16* __restrict__ Bh_g,
                 const __nv_bfloat16* __restrict__ Bl_g,
                 const float* __restrict__ bias,
                 float* __restrict__ C)
{
    extern __shared__ char sm[];
    const uint32_t sb = smem_u32(sm);
    GemmCtx g = gemm_ctx_init(sb);
    const int tid = g.tid;

    auto ldg_a = [&](int kc, float4* a4) {
#pragma unroll
        for (int s = 0; s < 2; s++) {
            const int idx = tid + s * 256;
            const int r = idx >> 2, c = idx & 3;
            const float* p = A_g + (size_t)(g.bm + r) * 256 + kc * 32 + c * 8;
            a4[s * 2 + 0] = *reinterpret_cast<const float4*>(p);
            a4[s * 2 + 1] = *reinterpret_cast<const float4*>(p + 4);
        }
    };
    auto sts_a = [&](int st, const float4* a4) {
#pragma unroll
        for (int s = 0; s < 2; s++) {
            const int idx = tid + s * 256;
            const int r = idx >> 2, c = idx & 3;
            const uint32_t so = (uint32_t)(st * STAGEB) + swz_off(r, c);
            const float4 v0 = a4[s * 2 + 0], v1 = a4[s * 2 + 1];
            uint4 hp, lp;
            hp.x = pack_hi2(v0.x, v0.y); hp.y = pack_hi2(v0.z, v0.w);
            hp.z = pack_hi2(v1.x, v1.y); hp.w = pack_hi2(v1.z, v1.w);
            lp.x = pack_lo2(v0.x, v0.y); lp.y = pack_lo2(v0.z, v0.w);
            lp.z = pack_lo2(v1.x, v1.y); lp.w = pack_lo2(v1.z, v1.w);
            *reinterpret_cast<uint4*>(sm + OFF_AH + so) = hp;
            *reinterpret_cast<uint4*>(sm + OFF_AL + so) = lp;
        }
    };
    auto cp_b = [&](int kc, int st) {
        const int r = tid >> 2, c = tid & 3;
        const uint32_t so = (uint32_t)(st * STAGEB) + swz_off(r, c);
        const size_t go = (size_t)(g.bn + r) * 256 + kc * 32 + c * 8;
        cp16(sb + so + OFF_BH, Bh_g + go);
        cp16(sb + so + OFF_BL, Bl_g + go);
    };

    float acc[2][4][4];
#pragma unroll
    for (int mt = 0; mt < 2; mt++)
#pragma unroll
        for (int nt = 0; nt < 4; nt++)
#pragma unroll
            for (int q = 0; q < 4; q++) acc[mt][nt][q] = 0.f;

    cp_b(0, 0);
    asm volatile("cp.async.commit_group;" ::: "memory");
    cp_b(1, 1);
    asm volatile("cp.async.commit_group;" ::: "memory");

    float4 areg[4];
    ldg_a(0, areg);
    sts_a(0, areg);
    ldg_a(1, areg);

    for (int kc = 0; kc < NCHUNK; kc++) {
        if (kc + 1 < NCHUNK) sts_a((kc + 1) % 3, areg);
        if (kc + 2 < NCHUNK) ldg_a(kc + 2, areg);
        asm volatile("cp.async.wait_group 1;" ::: "memory");
        __syncthreads();
        if (kc + 2 < NCHUNK) cp_b(kc + 2, (kc + 2) % 3);
        asm volatile("cp.async.commit_group;" ::: "memory");
        gemm_compute_chunk32(g, sb + (uint32_t)((kc % 3) * STAGEB), acc);
    }
    gemm_epilogue(g, acc, bias, C);
}

// ---------------------------------------------------------------------------
// Neighborhood aggregation (unchanged from R13): 8x16 strips, 3 CTAs/SM,
// cp.async staging, rolling 7x7 register window, bf16 hi/lo output.
// ---------------------------------------------------------------------------
#define AGTILE 16
#define STRIPR 8
#define NRMAX  14
#define HALO   22
#define WPAD   52
#define VS_FLOATS (NRMAX * HALO * HD)             // 9856
#define WS_FLOATS (128 * WPAD)                    // 6656
#define AGG_SMEM  ((VS_FLOATS + WS_FLOATS) * 4)   // 66048

__device__ __forceinline__ constexpr int shifts_fn(int CLS, int tj) {
    return CLS == 0 ? (tj > 3 ? tj - 3 : 0)
         : CLS == 1 ? tj
         : (tj < 12 ? tj : 12);
}

template <int CLS>
__device__ __forceinline__ void agg_row(
    const float* __restrict__ vs, const float* __restrict__ ws,
    int i0, int j0, int rs, int ti,
    int warp, int lane, int b, int head,
    __nv_bfloat16* __restrict__ oh, __nv_bfloat16* __restrict__ ol)
{
    const int i  = i0 + ti;
    const int si = min(max(i - 3, 0), IMG - 7) - rs;
    const float* vrow = vs + si * (HALO * HD) + lane;

    float v[7][7];
#pragma unroll
    for (int ki = 0; ki < 7; ki++)
#pragma unroll
        for (int kj = 0; kj < 7; kj++)
            v[ki][kj] = vrow[(ki * HALO + kj) * HD];

#pragma unroll
    for (int tj = 0; tj < AGTILE; tj++) {
        const int sh = shifts_fn(CLS, tj);
        if (tj > 0 && sh != shifts_fn(CLS, tj - 1)) {
            const int c = sh + 6;
            const int slot = c % 7;
#pragma unroll
            for (int ki = 0; ki < 7; ki++)
                v[ki][slot] = vrow[(ki * HALO + c) * HD];
        }

        const int pl = warp * AGTILE + tj;
        const float4* wq = reinterpret_cast<const float4*>(ws + pl * WPAD);
        float a0 = 0.f, a1 = 0.f, a2 = 0.f, a3 = 0.f;
#pragma unroll
        for (int q = 0; q < 13; q++) {
            const float4 wv = wq[q];
#pragma unroll
            for (int e = 0; e < 4; e++) {
                const int idx = q * 4 + e;
                if (idx < 49) {
                    const int ki = idx / 7, kj = idx % 7;
                    const float we = (e == 0) ? wv.x : (e == 1) ? wv.y
                                   : (e == 2) ? wv.z : wv.w;
                    const float vv = v[ki][(sh + kj) % 7];
                    if (e == 0)      a0 += we * vv;
                    else if (e == 1) a1 += we * vv;
                    else if (e == 2) a2 += we * vv;
                    else             a3 += we * vv;
                }
            }
        }
        const float acc = (a0 + a1) + (a2 + a3);

        const int j = j0 + tj;
        const size_t oidx = (((size_t)b * IMG + i) * IMG + j) * CDIM
                          + head * HD + lane;
        __nv_bfloat16 hi = __float2bfloat16(acc);
        oh[oidx] = hi;
        ol[oidx] = __float2bfloat16(acc - __bfloat162float(hi));
    }
}

__global__ void __launch_bounds__(256, 3)
agg_kernel(const float* __restrict__ v,
           const float* __restrict__ attn,
           __nv_bfloat16* __restrict__ oh,
           __nv_bfloat16* __restrict__ ol)
{
    const int st  = blockIdx.x >> 3;
    const int jt  = blockIdx.x & 7;
    const int head = blockIdx.y;
    const int b    = blockIdx.z;
    const int i0 = st * STRIPR;
    const int j0 = jt * AGTILE;

    const int rs = min(max(i0 - 3, 0), IMG - 7);
    const int re = min(max(i0 + STRIPR - 4, 0), IMG - 7) + 6;
    const int cs = min(max(j0 - 3, 0), IMG - 7);
    const int ce = min(max(j0 + AGTILE - 4, 0), IMG - 7) + 6;
    const int nr = re - rs + 1;            // <= 14
    const int nc = ce - cs + 1;            // <= 22

    extern __shared__ float sm_f[];
    float* vs = sm_f;
    float* ws = sm_f + VS_FLOATS;
    const uint32_t sb = smem_u32(sm_f);

    const int tid = threadIdx.x;
    const int warp = tid >> 5;
    const int lane = tid & 31;

    const float* vbase = v + (size_t)b * IMG * IMG * CDIM + head * HD;
    const int nquads = nr * nc * (HD / 4);
    for (int idx = tid; idx < nquads; idx += 256) {
        const int d4 = idx & 7;
        const int p  = idx >> 3;
        const int rr = p / nc;
        const int cc = p - rr * nc;
        cp16(sb + (uint32_t)(((rr * HALO + cc) * HD + d4 * 4) * 4),
             vbase + ((size_t)(rs + rr) * IMG + (cs + cc)) * CDIM + d4 * 4);
    }

    const float* abase = attn + ((((size_t)b * HDS + head) * IMG + i0) * IMG + j0) * 49;
    const uint32_t wsb = sb + (uint32_t)(VS_FLOATS * 4);
    for (int idx = tid; idx < 128 * 49; idx += 256) {
        const int pl = idx / 49;
        const int k  = idx - pl * 49;
        const int ti = pl >> 4;
        const int tj = pl & 15;
        cp4(wsb + (uint32_t)((pl * WPAD + k) * 4),
            abase + ((size_t)ti * IMG + tj) * 49 + k);
    }
    asm volatile("cp.async.commit_group;" ::: "memory");
    asm volatile("cp.async.wait_group 0;" ::: "memory");
    __syncthreads();

    if (j0 == 0)
        agg_row<0>(vs, ws, i0, j0, rs, warp, warp, lane, b, head, oh, ol);
    else if (j0 == IMG - AGTILE)
        agg_row<2>(vs, ws, i0, j0, rs, warp, warp, lane, b, head, oh, ol);
    else
        agg_row<1>(vs, ws, i0, j0, rs, warp, warp, lane, b, head, oh, ol);
}

// ---------------------------------------------------------------------------
extern "C" void kernel_launch(void* const* d_in, const int* in_sizes, int n_in,
                              void* d_out, int out_size)
{
    const float* x    = (const float*)d_in[0];
    const float* attn = (const float*)d_in[1];
    const float* Wv   = (const float*)d_in[2];
    const float* bv   = (const float*)d_in[3];
    const float* Wp   = (const float*)d_in[4];
    const float* bp   = (const float*)d_in[5];
    float*       out  = (float*)d_out;

    void *pv, *poh, *pol, *pwvh, *pwvl, *pwph, *pwpl;
    cudaGetSymbolAddress(&pv,   g_v);
    cudaGetSymbolAddress(&poh,  g_oh);
    cudaGetSymbolAddress(&pol,  g_ol);
    cudaGetSymbolAddress(&pwvh, g_wvh);
    cudaGetSymbolAddress(&pwvl, g_wvl);
    cudaGetSymbolAddress(&pwph, g_wph);
    cudaGetSymbolAddress(&pwpl, g_wpl);

    cudaFuncSetAttribute(gemm_f32a_kernel,
                         cudaFuncAttributeMaxDynamicSharedMemorySize, GM_SMEM);
    cudaFuncSetAttribute(gemm_bf16a_kernel,
                         cudaFuncAttributeMaxDynamicSharedMemorySize, GM_SMEM);
    cudaFuncSetAttribute(agg_kernel,
                         cudaFuncAttributeMaxDynamicSharedMemorySize, AGG_SMEM);

    split_w_kernel<<<256, 256>>>(Wv, (__nv_bfloat16*)pwvh, (__nv_bfloat16*)pwvl,
                                 Wp, (__nv_bfloat16*)pwph, (__nv_bfloat16*)pwpl);

    dim3 ggrid(1024, 4);
    gemm_f32a_kernel<<<ggrid, 256, GM_SMEM>>>(x,
                                              (__nv_bfloat16*)pwvh, (__nv_bfloat16*)pwvl,
                                              bv, (float*)pv);

    dim3 agrid(128, HDS, 8);
    agg_kernel<<<agrid, 256, AGG_SMEM>>>((float*)pv, attn,
                                         (__nv_bfloat16*)poh, (__nv_bfloat16*)pol);

    gemm_bf16a_kernel<<<ggrid, 256, GM_SMEM>>>((__nv_bfloat16*)poh, (__nv_bfloat16*)pol,
                                               (__nv_bfloat16*)pwph, (__nv_bfloat16*)pwpl,
                                               bp, out);
}

// round 15
// speedup vs baseline: 1.3560x; 1.3560x over previous
#include <cuda_runtime.h>
#include <cuda_bf16.h>
#include <cstdint>

#define IMG   128
#define CDIM  256
#define HDS   8
#define HD    32
#define NELEM 33554432   // 131072 * 256

// Scratch (allocation-free rule: device globals)
__device__ float g_v[NELEM];        // v buffer fp32
__device__ float g_o[NELEM];        // agg output fp32
__device__ float g_wv32[65536];     // Wv rounded to tf32
__device__ float g_wp32[65536];     // Wp rounded to tf32

// ---------------------------------------------------------------------------
// helpers
// ---------------------------------------------------------------------------
__device__ __forceinline__ uint32_t smem_u32(const void* p) {
    uint32_t a;
    asm("{ .reg .u64 t; cvta.to.shared.u64 t, %1; cvt.u32.u64 %0, t; }"
        : "=r"(a) : "l"(p));
    return a;
}
__device__ __forceinline__ void cp16(uint32_t saddr, const void* g) {
    asm volatile("cp.async.cg.shared.global [%0], [%1], 16;"
                 :: "r"(saddr), "l"(g));
}
__device__ __forceinline__ void cp4(uint32_t saddr, const void* g) {
    asm volatile("cp.async.ca.shared.global [%0], [%1], 4;"
                 :: "r"(saddr), "l"(g));
}
__device__ __forceinline__ void ldm_x4(uint32_t* d, uint32_t a) {
    asm volatile("ldmatrix.sync.aligned.m8n8.x4.shared.b16 {%0,%1,%2,%3}, [%4];"
                 : "=r"(d[0]), "=r"(d[1]), "=r"(d[2]), "=r"(d[3]) : "r"(a));
}
__device__ __forceinline__ void cvt_tf32(uint32_t& x) {
    asm("cvt.rna.tf32.f32 %0, %0;" : "+r"(x));
}
__device__ __forceinline__ void mma_tf32(float* c, const uint32_t* a, const uint32_t* b) {
    asm volatile("mma.sync.aligned.m16n8k8.row.col.f32.tf32.tf32.f32 "
                 "{%0,%1,%2,%3}, {%4,%5,%6,%7}, {%8,%9}, {%0,%1,%2,%3};"
                 : "+f"(c[0]), "+f"(c[1]), "+f"(c[2]), "+f"(c[3])
                 : "r"(a[0]), "r"(a[1]), "r"(a[2]), "r"(a[3]),
                   "r"(b[0]), "r"(b[1]));
}

// ---------------------------------------------------------------------------
// W round: fp32 -> tf32 (RNA), both weight matrices
// ---------------------------------------------------------------------------
__global__ void round_w_kernel(const float* __restrict__ W1, float* __restrict__ O1,
                               const float* __restrict__ W2, float* __restrict__ O2)
{
    int i = blockIdx.x * 256 + threadIdx.x;
    uint32_t a = __float_as_uint(W1[i]);
    cvt_tf32(a);
    O1[i] = __uint_as_float(a);
    uint32_t b = __float_as_uint(W2[i]);
    cvt_tf32(b);
    O2[i] = __uint_as_float(b);
}

// ---------------------------------------------------------------------------
// TF32 GEMM: C[M,256] = A[M,256] @ W[256,256]^T + bias
//  CTA tile 128x128, 8 warps (4M x 2N), warp tile 32x64.
//  3-stage cp.async pipeline, BK=32 (4 k8 steps/chunk), SW128 swizzle
//  (rows 128B; seg' = seg ^ (row&7)), ldmatrix-on-fp32 fragments,
//  A rounded to tf32 in-register; B pre-rounded in gmem.
// Stage: A(16384) | B(16384) = 32768 B; 3 stages = 98304 -> 2 CTAs/SM.
// ---------------------------------------------------------------------------
#define NCHUNK 8
#define ROWB   128
#define OFF_A  0
#define OFF_B  16384
#define STAGEB 32768
#define GM_SMEM (3 * STAGEB)       // 98304

__device__ __forceinline__ uint32_t swz(int r, int seg) {
    return (uint32_t)(r * ROWB) + (uint32_t)((seg ^ (r & 7)) << 4);
}

__global__ void __launch_bounds__(256, 2)
gemm_tf32_kernel(const float* __restrict__ A_g,
                 const float* __restrict__ B_g,
                 const float* __restrict__ bias,
                 float* __restrict__ C)
{
    extern __shared__ char sm[];
    const uint32_t sb = smem_u32(sm);
    const int tid  = threadIdx.x;
    const int wid  = tid >> 5, lane = tid & 31;
    const int bm   = blockIdx.x * 128;
    const int bn   = blockIdx.y * 128;
    const int m0   = (wid & 3) * 32;
    const int n0   = (wid >> 2) * 64;

    // lane-local fragment addressing
    const int a_row  = lane & 15;                       // + m0 + mt*16
    const int a_segl = lane >> 4;                       // k-half {0,1}
    const int b_row  = (lane & 7) + (lane >> 4) * 8;    // + n0 + np*16
    const int b_segl = (lane >> 3) & 1;
    const uint32_t lane_xor = (uint32_t)(lane & 7);     // row&7 (bases mult of 8)

    auto load_chunk = [&](int kc, int st) {
#pragma unroll
        for (int s = 0; s < 4; s++) {
            const int idx = tid + s * 256;              // 0..1023
            const int r = idx >> 3, seg = idx & 7;
            const uint32_t so = (uint32_t)(st * STAGEB) + swz(r, seg);
            cp16(sb + so + OFF_A,
                 A_g + (size_t)(bm + r) * 256 + kc * 32 + seg * 4);
            cp16(sb + so + OFF_B,
                 B_g + (size_t)(bn + r) * 256 + kc * 32 + seg * 4);
        }
    };

    float acc[2][8][4];
#pragma unroll
    for (int mt = 0; mt < 2; mt++)
#pragma unroll
        for (int nt = 0; nt < 8; nt++)
#pragma unroll
            for (int q = 0; q < 4; q++) acc[mt][nt][q] = 0.f;

    load_chunk(0, 0);
    asm volatile("cp.async.commit_group;" ::: "memory");
    load_chunk(1, 1);
    asm volatile("cp.async.commit_group;" ::: "memory");

    int sr = 0, sw = 2;
    for (int kc = 0; kc < NCHUNK; kc++) {
        asm volatile("cp.async.wait_group 1;" ::: "memory");
        __syncthreads();
        if (kc + 2 < NCHUNK) {
            load_chunk(kc + 2, sw);
            if (++sw == 3) sw = 0;
        }
        asm volatile("cp.async.commit_group;" ::: "memory");

        const uint32_t stb = sb + (uint32_t)(sr * STAGEB);
#pragma unroll
        for (int k8 = 0; k8 < 4; k8++) {
            const uint32_t a_soff = (uint32_t)(((k8 * 2 + a_segl) ^ lane_xor) << 4);
            const uint32_t b_soff = (uint32_t)(((k8 * 2 + b_segl) ^ lane_xor) << 4);
            uint32_t AF[2][4];
#pragma unroll
            for (int mt = 0; mt < 2; mt++) {
                const uint32_t aaddr = stb + OFF_A
                    + (uint32_t)((m0 + mt * 16 + a_row) * ROWB) + a_soff;
                ldm_x4(AF[mt], aaddr);
                cvt_tf32(AF[mt][0]); cvt_tf32(AF[mt][1]);
                cvt_tf32(AF[mt][2]); cvt_tf32(AF[mt][3]);
            }
#pragma unroll
            for (int np = 0; np < 4; np++) {
                const uint32_t baddr = stb + OFF_B
                    + (uint32_t)((n0 + np * 16 + b_row) * ROWB) + b_soff;
                uint32_t bf[4];
                ldm_x4(bf, baddr);
                const int nt0 = 2 * np, nt1 = 2 * np + 1;
                mma_tf32(acc[0][nt0], AF[0], bf + 0);
                mma_tf32(acc[1][nt0], AF[1], bf + 0);
                mma_tf32(acc[0][nt1], AF[0], bf + 2);
                mma_tf32(acc[1][nt1], AF[1], bf + 2);
            }
        }
        if (++sr == 3) sr = 0;
    }

    // epilogue
#pragma unroll
    for (int mt = 0; mt < 2; mt++) {
        const int row = bm + m0 + mt * 16 + (lane >> 2);
#pragma unroll
        for (int nt = 0; nt < 8; nt++) {
            const int col = bn + n0 + nt * 8 + 2 * (lane & 3);
            const float b0 = __ldg(bias + col), b1 = __ldg(bias + col + 1);
            float2 v0, v1;
            v0.x = acc[mt][nt][0] + b0; v0.y = acc[mt][nt][1] + b1;
            v1.x = acc[mt][nt][2] + b0; v1.y = acc[mt][nt][3] + b1;
            *reinterpret_cast<float2*>(C + (size_t)row * 256 + col) = v0;
            *reinterpret_cast<float2*>(C + (size_t)(row + 8) * 256 + col) = v1;
        }
    }
}

// ---------------------------------------------------------------------------
// Neighborhood aggregation (R13 structure): 8x16 strips, 3 CTAs/SM,
// cp.async staging, rolling 7x7 register window, fp32 output.
// ---------------------------------------------------------------------------
#define AGTILE 16
#define STRIPR 8
#define NRMAX  14
#define HALO   22
#define WPAD   52
#define VS_FLOATS (NRMAX * HALO * HD)             // 9856
#define WS_FLOATS (128 * WPAD)                    // 6656
#define AGG_SMEM  ((VS_FLOATS + WS_FLOATS) * 4)   // 66048

__device__ __forceinline__ constexpr int shifts_fn(int CLS, int tj) {
    return CLS == 0 ? (tj > 3 ? tj - 3 : 0)
         : CLS == 1 ? tj
         : (tj < 12 ? tj : 12);
}

template <int CLS>
__device__ __forceinline__ void agg_row(
    const float* __restrict__ vs, const float* __restrict__ ws,
    int i0, int j0, int rs, int ti,
    int warp, int lane, int b, int head,
    float* __restrict__ o)
{
    const int i  = i0 + ti;
    const int si = min(max(i - 3, 0), IMG - 7) - rs;
    const float* vrow = vs + si * (HALO * HD) + lane;

    float v[7][7];
#pragma unroll
    for (int ki = 0; ki < 7; ki++)
#pragma unroll
        for (int kj = 0; kj < 7; kj++)
            v[ki][kj] = vrow[(ki * HALO + kj) * HD];

#pragma unroll
    for (int tj = 0; tj < AGTILE; tj++) {
        const int sh = shifts_fn(CLS, tj);
        if (tj > 0 && sh != shifts_fn(CLS, tj - 1)) {
            const int c = sh + 6;
            const int slot = c % 7;
#pragma unroll
            for (int ki = 0; ki < 7; ki++)
                v[ki][slot] = vrow[(ki * HALO + c) * HD];
        }

        const int pl = warp * AGTILE + tj;
        const float4* wq = reinterpret_cast<const float4*>(ws + pl * WPAD);
        float a0 = 0.f, a1 = 0.f, a2 = 0.f, a3 = 0.f;
#pragma unroll
        for (int q = 0; q < 13; q++) {
            const float4 wv = wq[q];
#pragma unroll
            for (int e = 0; e < 4; e++) {
                const int idx = q * 4 + e;
                if (idx < 49) {
                    const int ki = idx / 7, kj = idx % 7;
                    const float we = (e == 0) ? wv.x : (e == 1) ? wv.y
                                   : (e == 2) ? wv.z : wv.w;
                    const float vv = v[ki][(sh + kj) % 7];
                    if (e == 0)      a0 += we * vv;
                    else if (e == 1) a1 += we * vv;
                    else if (e == 2) a2 += we * vv;
                    else             a3 += we * vv;
                }
            }
        }
        const float acc = (a0 + a1) + (a2 + a3);

        const int j = j0 + tj;
        o[(((size_t)b * IMG + i) * IMG + j) * CDIM + head * HD + lane] = acc;
    }
}

__global__ void __launch_bounds__(256, 3)
agg_kernel(const float* __restrict__ v,
           const float* __restrict__ attn,
           float* __restrict__ o)
{
    const int st  = blockIdx.x >> 3;
    const int jt  = blockIdx.x & 7;
    const int head = blockIdx.y;
    const int b    = blockIdx.z;
    const int i0 = st * STRIPR;
    const int j0 = jt * AGTILE;

    const int rs = min(max(i0 - 3, 0), IMG - 7);
    const int re = min(max(i0 + STRIPR - 4, 0), IMG - 7) + 6;
    const int cs = min(max(j0 - 3, 0), IMG - 7);
    const int ce = min(max(j0 + AGTILE - 4, 0), IMG - 7) + 6;
    const int nr = re - rs + 1;            // <= 14
    const int nc = ce - cs + 1;            // <= 22

    extern __shared__ float sm_f[];
    float* vs = sm_f;
    float* ws = sm_f + VS_FLOATS;
    const uint32_t sb = smem_u32(sm_f);

    const int tid = threadIdx.x;
    const int warp = tid >> 5;
    const int lane = tid & 31;

    const float* vbase = v + (size_t)b * IMG * IMG * CDIM + head * HD;
    const int nquads = nr * nc * (HD / 4);
    for (int idx = tid; idx < nquads; idx += 256) {
        const int d4 = idx & 7;
        const int p  = idx >> 3;
        const int rr = p / nc;
        const int cc = p - rr * nc;
        cp16(sb + (uint32_t)(((rr * HALO + cc) * HD + d4 * 4) * 4),
             vbase + ((size_t)(rs + rr) * IMG + (cs + cc)) * CDIM + d4 * 4);
    }

    const float* abase = attn + ((((size_t)b * HDS + head) * IMG + i0) * IMG + j0) * 49;
    const uint32_t wsb = sb + (uint32_t)(VS_FLOATS * 4);
    for (int idx = tid; idx < 128 * 49; idx += 256) {
        const int pl = idx / 49;
        const int k  = idx - pl * 49;
        const int ti = pl >> 4;
        const int tj = pl & 15;
        cp4(wsb + (uint32_t)((pl * WPAD + k) * 4),
            abase + ((size_t)ti * IMG + tj) * 49 + k);
    }
    asm volatile("cp.async.commit_group;" ::: "memory");
    asm volatile("cp.async.wait_group 0;" ::: "memory");
    __syncthreads();

    if (j0 == 0)
        agg_row<0>(vs, ws, i0, j0, rs, warp, warp, lane, b, head, o);
    else if (j0 == IMG - AGTILE)
        agg_row<2>(vs, ws, i0, j0, rs, warp, warp, lane, b, head, o);
    else
        agg_row<1>(vs, ws, i0, j0, rs, warp, warp, lane, b, head, o);
}

// ---------------------------------------------------------------------------
extern "C" void kernel_launch(void* const* d_in, const int* in_sizes, int n_in,
                              void* d_out, int out_size)
{
    const float* x    = (const float*)d_in[0];
    const float* attn = (const float*)d_in[1];
    const float* Wv   = (const float*)d_in[2];
    const float* bv   = (const float*)d_in[3];
    const float* Wp   = (const float*)d_in[4];
    const float* bp   = (const float*)d_in[5];
    float*       out  = (float*)d_out;

    void *pv, *po, *pwv, *pwp;
    cudaGetSymbolAddress(&pv,  g_v);
    cudaGetSymbolAddress(&po,  g_o);
    cudaGetSymbolAddress(&pwv, g_wv32);
    cudaGetSymbolAddress(&pwp, g_wp32);

    cudaFuncSetAttribute(gemm_tf32_kernel,
                         cudaFuncAttributeMaxDynamicSharedMemorySize, GM_SMEM);
    cudaFuncSetAttribute(agg_kernel,
                         cudaFuncAttributeMaxDynamicSharedMemorySize, AGG_SMEM);

    round_w_kernel<<<256, 256>>>(Wv, (float*)pwv, Wp, (float*)pwp);

    dim3 ggrid(1024, 2);
    gemm_tf32_kernel<<<ggrid, 256, GM_SMEM>>>(x, (float*)pwv, bv, (float*)pv);

    dim3 agrid(128, HDS, 8);
    agg_kernel<<<agrid, 256, AGG_SMEM>>>((float*)pv, attn, (float*)po);

    gemm_tf32_kernel<<<ggrid, 256, GM_SMEM>>>((float*)po, (float*)pwp, bp, out);
}

// round 16
// speedup vs baseline: 1.3638x; 1.0058x over previous
#include <cuda_runtime.h>
#include <cuda_bf16.h>
#include <cstdint>

#define IMG   128
#define CDIM  256
#define HDS   8
#define HD    32
#define NELEM 33554432   // 131072 * 256

// Scratch (allocation-free rule: device globals)
__device__ float g_v[NELEM];        // v buffer fp32
__device__ float g_o[NELEM];        // agg output fp32
__device__ float g_wv32[65536];     // Wv rounded to tf32
__device__ float g_wp32[65536];     // Wp rounded to tf32

// ---------------------------------------------------------------------------
// helpers
// ---------------------------------------------------------------------------
__device__ __forceinline__ uint32_t smem_u32(const void* p) {
    uint32_t a;
    asm("{ .reg .u64 t; cvta.to.shared.u64 t, %1; cvt.u32.u64 %0, t; }"
        : "=r"(a) : "l"(p));
    return a;
}
__device__ __forceinline__ void cp16(uint32_t saddr, const void* g) {
    asm volatile("cp.async.cg.shared.global [%0], [%1], 16;"
                 :: "r"(saddr), "l"(g));
}
__device__ __forceinline__ void cp4(uint32_t saddr, const void* g) {
    asm volatile("cp.async.ca.shared.global [%0], [%1], 4;"
                 :: "r"(saddr), "l"(g));
}
__device__ __forceinline__ void ldm_x4(uint32_t* d, uint32_t a) {
    asm volatile("ldmatrix.sync.aligned.m8n8.x4.shared.b16 {%0,%1,%2,%3}, [%4];"
                 : "=r"(d[0]), "=r"(d[1]), "=r"(d[2]), "=r"(d[3]) : "r"(a));
}
__device__ __forceinline__ void cvt_tf32(uint32_t& x) {
    asm("cvt.rna.tf32.f32 %0, %0;" : "+r"(x));
}
__device__ __forceinline__ void mma_tf32(float* c, const uint32_t* a, const uint32_t* b) {
    asm volatile("mma.sync.aligned.m16n8k8.row.col.f32.tf32.tf32.f32 "
                 "{%0,%1,%2,%3}, {%4,%5,%6,%7}, {%8,%9}, {%0,%1,%2,%3};"
                 : "+f"(c[0]), "+f"(c[1]), "+f"(c[2]), "+f"(c[3])
                 : "r"(a[0]), "r"(a[1]), "r"(a[2]), "r"(a[3]),
                   "r"(b[0]), "r"(b[1]));
}

// ---------------------------------------------------------------------------
// W round: fp32 -> tf32 (RNA), both weight matrices
// ---------------------------------------------------------------------------
__global__ void round_w_kernel(const float* __restrict__ W1, float* __restrict__ O1,
                               const float* __restrict__ W2, float* __restrict__ O2)
{
    int i = blockIdx.x * 256 + threadIdx.x;
    uint32_t a = __float_as_uint(W1[i]);
    cvt_tf32(a);
    O1[i] = __uint_as_float(a);
    uint32_t b = __float_as_uint(W2[i]);
    cvt_tf32(b);
    O2[i] = __uint_as_float(b);
}

// ---------------------------------------------------------------------------
// TF32 GEMM: C[M,256] = A[M,256] @ W[256,256]^T + bias
//  CTA tile 128x128, 8 warps (4M x 2N), warp tile 32x64.
//  3-stage cp.async pipeline, BK=32 (4 k8 steps/chunk), SW128 swizzle,
//  ldmatrix-on-fp32 fragments, A rounded to tf32 in-register.
//  GRID = (2, 1024): bn = blockIdx.x, bm = blockIdx.y -> the two CTAs
//  sharing an A-tile are adjacent in launch order, so the second one's
//  A reads hit L2 (A DRAM traffic halves).
// Stage: A(16384) | B(16384) = 32768 B; 3 stages = 98304 -> 2 CTAs/SM.
// ---------------------------------------------------------------------------
#define NCHUNK 8
#define ROWB   128
#define OFF_A  0
#define OFF_B  16384
#define STAGEB 32768
#define GM_SMEM (3 * STAGEB)       // 98304

__device__ __forceinline__ uint32_t swz(int r, int seg) {
    return (uint32_t)(r * ROWB) + (uint32_t)((seg ^ (r & 7)) << 4);
}

__global__ void __launch_bounds__(256, 2)
gemm_tf32_kernel(const float* __restrict__ A_g,
                 const float* __restrict__ B_g,
                 const float* __restrict__ bias,
                 float* __restrict__ C)
{
    extern __shared__ char sm[];
    const uint32_t sb = smem_u32(sm);
    const int tid  = threadIdx.x;
    const int wid  = tid >> 5, lane = tid & 31;
    const int bm   = blockIdx.y * 128;       // M from grid.y (1024)
    const int bn   = blockIdx.x * 128;       // N from grid.x (2)
    const int m0   = (wid & 3) * 32;
    const int n0   = (wid >> 2) * 64;

    const int a_row  = lane & 15;
    const int a_segl = lane >> 4;
    const int b_row  = (lane & 7) + (lane >> 4) * 8;
    const int b_segl = (lane >> 3) & 1;
    const uint32_t lane_xor = (uint32_t)(lane & 7);

    auto load_chunk = [&](int kc, int st) {
#pragma unroll
        for (int s = 0; s < 4; s++) {
            const int idx = tid + s * 256;
            const int r = idx >> 3, seg = idx & 7;
            const uint32_t so = (uint32_t)(st * STAGEB) + swz(r, seg);
            cp16(sb + so + OFF_A,
                 A_g + (size_t)(bm + r) * 256 + kc * 32 + seg * 4);
            cp16(sb + so + OFF_B,
                 B_g + (size_t)(bn + r) * 256 + kc * 32 + seg * 4);
        }
    };

    float acc[2][8][4];
#pragma unroll
    for (int mt = 0; mt < 2; mt++)
#pragma unroll
        for (int nt = 0; nt < 8; nt++)
#pragma unroll
            for (int q = 0; q < 4; q++) acc[mt][nt][q] = 0.f;

    load_chunk(0, 0);
    asm volatile("cp.async.commit_group;" ::: "memory");
    load_chunk(1, 1);
    asm volatile("cp.async.commit_group;" ::: "memory");

    int sr = 0, sw = 2;
    for (int kc = 0; kc < NCHUNK; kc++) {
        asm volatile("cp.async.wait_group 1;" ::: "memory");
        __syncthreads();
        if (kc + 2 < NCHUNK) {
            load_chunk(kc + 2, sw);
            if (++sw == 3) sw = 0;
        }
        asm volatile("cp.async.commit_group;" ::: "memory");

        const uint32_t stb = sb + (uint32_t)(sr * STAGEB);
#pragma unroll
        for (int k8 = 0; k8 < 4; k8++) {
            const uint32_t a_soff = (uint32_t)(((k8 * 2 + a_segl) ^ lane_xor) << 4);
            const uint32_t b_soff = (uint32_t)(((k8 * 2 + b_segl) ^ lane_xor) << 4);
            uint32_t AF[2][4];
#pragma unroll
            for (int mt = 0; mt < 2; mt++) {
                const uint32_t aaddr = stb + OFF_A
                    + (uint32_t)((m0 + mt * 16 + a_row) * ROWB) + a_soff;
                ldm_x4(AF[mt], aaddr);
                cvt_tf32(AF[mt][0]); cvt_tf32(AF[mt][1]);
                cvt_tf32(AF[mt][2]); cvt_tf32(AF[mt][3]);
            }
#pragma unroll
            for (int np = 0; np < 4; np++) {
                const uint32_t baddr = stb + OFF_B
                    + (uint32_t)((n0 + np * 16 + b_row) * ROWB) + b_soff;
                uint32_t bf[4];
                ldm_x4(bf, baddr);
                const int nt0 = 2 * np, nt1 = 2 * np + 1;
                mma_tf32(acc[0][nt0], AF[0], bf + 0);
                mma_tf32(acc[1][nt0], AF[1], bf + 0);
                mma_tf32(acc[0][nt1], AF[0], bf + 2);
                mma_tf32(acc[1][nt1], AF[1], bf + 2);
            }
        }
        if (++sr == 3) sr = 0;
    }

#pragma unroll
    for (int mt = 0; mt < 2; mt++) {
        const int row = bm + m0 + mt * 16 + (lane >> 2);
#pragma unroll
        for (int nt = 0; nt < 8; nt++) {
            const int col = bn + n0 + nt * 8 + 2 * (lane & 3);
            const float b0 = __ldg(bias + col), b1 = __ldg(bias + col + 1);
            float2 v0, v1;
            v0.x = acc[mt][nt][0] + b0; v0.y = acc[mt][nt][1] + b1;
            v1.x = acc[mt][nt][2] + b0; v1.y = acc[mt][nt][3] + b1;
            *reinterpret_cast<float2*>(C + (size_t)row * 256 + col) = v0;
            *reinterpret_cast<float2*>(C + (size_t)(row + 8) * 256 + col) = v1;
        }
    }
}

// ---------------------------------------------------------------------------
// Neighborhood aggregation (unchanged from R15): 8x16 strips, 3 CTAs/SM,
// cp.async staging, rolling 7x7 register window, fp32 output.
// ---------------------------------------------------------------------------
#define AGTILE 16
#define STRIPR 8
#define NRMAX  14
#define HALO   22
#define WPAD   52
#define VS_FLOATS (NRMAX * HALO * HD)             // 9856
#define WS_FLOATS (128 * WPAD)                    // 6656
#define AGG_SMEM  ((VS_FLOATS + WS_FLOATS) * 4)   // 66048

__device__ __forceinline__ constexpr int shifts_fn(int CLS, int tj) {
    return CLS == 0 ? (tj > 3 ? tj - 3 : 0)
         : CLS == 1 ? tj
         : (tj < 12 ? tj : 12);
}

template <int CLS>
__device__ __forceinline__ void agg_row(
    const float* __restrict__ vs, const float* __restrict__ ws,
    int i0, int j0, int rs, int ti,
    int warp, int lane, int b, int head,
    float* __restrict__ o)
{
    const int i  = i0 + ti;
    const int si = min(max(i - 3, 0), IMG - 7) - rs;
    const float* vrow = vs + si * (HALO * HD) + lane;

    float v[7][7];
#pragma unroll
    for (int ki = 0; ki < 7; ki++)
#pragma unroll
        for (int kj = 0; kj < 7; kj++)
            v[ki][kj] = vrow[(ki * HALO + kj) * HD];

#pragma unroll
    for (int tj = 0; tj < AGTILE; tj++) {
        const int sh = shifts_fn(CLS, tj);
        if (tj > 0 && sh != shifts_fn(CLS, tj - 1)) {
            const int c = sh + 6;
            const int slot = c % 7;
#pragma unroll
            for (int ki = 0; ki < 7; ki++)
                v[ki][slot] = vrow[(ki * HALO + c) * HD];
        }

        const int pl = warp * AGTILE + tj;
        const float4* wq = reinterpret_cast<const float4*>(ws + pl * WPAD);
        float a0 = 0.f, a1 = 0.f, a2 = 0.f, a3 = 0.f;
#pragma unroll
        for (int q = 0; q < 13; q++) {
            const float4 wv = wq[q];
#pragma unroll
            for (int e = 0; e < 4; e++) {
                const int idx = q * 4 + e;
                if (idx < 49) {
                    const int ki = idx / 7, kj = idx % 7;
                    const float we = (e == 0) ? wv.x : (e == 1) ? wv.y
                                   : (e == 2) ? wv.z : wv.w;
                    const float vv = v[ki][(sh + kj) % 7];
                    if (e == 0)      a0 += we * vv;
                    else if (e == 1) a1 += we * vv;
                    else if (e == 2) a2 += we * vv;
                    else             a3 += we * vv;
                }
            }
        }
        const float acc = (a0 + a1) + (a2 + a3);

        const int j = j0 + tj;
        o[(((size_t)b * IMG + i) * IMG + j) * CDIM + head * HD + lane] = acc;
    }
}

__global__ void __launch_bounds__(256, 3)
agg_kernel(const float* __restrict__ v,
           const float* __restrict__ attn,
           float* __restrict__ o)
{
    const int st  = blockIdx.x >> 3;
    const int jt  = blockIdx.x & 7;
    const int head = blockIdx.y;
    const int b    = blockIdx.z;
    const int i0 = st * STRIPR;
    const int j0 = jt * AGTILE;

    const int rs = min(max(i0 - 3, 0), IMG - 7);
    const int re = min(max(i0 + STRIPR - 4, 0), IMG - 7) + 6;
    const int cs = min(max(j0 - 3, 0), IMG - 7);
    const int ce = min(max(j0 + AGTILE - 4, 0), IMG - 7) + 6;
    const int nr = re - rs + 1;            // <= 14
    const int nc = ce - cs + 1;            // <= 22

    extern __shared__ float sm_f[];
    float* vs = sm_f;
    float* ws = sm_f + VS_FLOATS;
    const uint32_t sb = smem_u32(sm_f);

    const int tid = threadIdx.x;
    const int warp = tid >> 5;
    const int lane = tid & 31;

    const float* vbase = v + (size_t)b * IMG * IMG * CDIM + head * HD;
    const int nquads = nr * nc * (HD / 4);
    for (int idx = tid; idx < nquads; idx += 256) {
        const int d4 = idx & 7;
        const int p  = idx >> 3;
        const int rr = p / nc;
        const int cc = p - rr * nc;
        cp16(sb + (uint32_t)(((rr * HALO + cc) * HD + d4 * 4) * 4),
             vbase + ((size_t)(rs + rr) * IMG + (cs + cc)) * CDIM + d4 * 4);
    }

    const float* abase = attn + ((((size_t)b * HDS + head) * IMG + i0) * IMG + j0) * 49;
    const uint32_t wsb = sb + (uint32_t)(VS_FLOATS * 4);
    for (int idx = tid; idx < 128 * 49; idx += 256) {
        const int pl = idx / 49;
        const int k  = idx - pl * 49;
        const int ti = pl >> 4;
        const int tj = pl & 15;
        cp4(wsb + (uint32_t)((pl * WPAD + k) * 4),
            abase + ((size_t)ti * IMG + tj) * 49 + k);
    }
    asm volatile("cp.async.commit_group;" ::: "memory");
    asm volatile("cp.async.wait_group 0;" ::: "memory");
    __syncthreads();

    if (j0 == 0)
        agg_row<0>(vs, ws, i0, j0, rs, warp, warp, lane, b, head, o);
    else if (j0 == IMG - AGTILE)
        agg_row<2>(vs, ws, i0, j0, rs, warp, warp, lane, b, head, o);
    else
        agg_row<1>(vs, ws, i0, j0, rs, warp, warp, lane, b, head, o);
}

// ---------------------------------------------------------------------------
extern "C" void kernel_launch(void* const* d_in, const int* in_sizes, int n_in,
                              void* d_out, int out_size)
{
    const float* x    = (const float*)d_in[0];
    const float* attn = (const float*)d_in[1];
    const float* Wv   = (const float*)d_in[2];
    const float* bv   = (const float*)d_in[3];
    const float* Wp   = (const float*)d_in[4];
    const float* bp   = (const float*)d_in[5];
    float*       out  = (float*)d_out;

    void *pv, *po, *pwv, *pwp;
    cudaGetSymbolAddress(&pv,  g_v);
    cudaGetSymbolAddress(&po,  g_o);
    cudaGetSymbolAddress(&pwv, g_wv32);
    cudaGetSymbolAddress(&pwp, g_wp32);

    cudaFuncSetAttribute(gemm_tf32_kernel,
                         cudaFuncAttributeMaxDynamicSharedMemorySize, GM_SMEM);
    cudaFuncSetAttribute(agg_kernel,
                         cudaFuncAttributeMaxDynamicSharedMemorySize, AGG_SMEM);

    round_w_kernel<<<256, 256>>>(Wv, (float*)pwv, Wp, (float*)pwp);

    dim3 ggrid(2, 1024);     // bn fastest -> A-sharing CTAs co-scheduled
    gemm_tf32_kernel<<<ggrid, 256, GM_SMEM>>>(x, (float*)pwv, bv, (float*)pv);

    dim3 agrid(128, HDS, 8);
    agg_kernel<<<agrid, 256, AGG_SMEM>>>((float*)pv, attn, (float*)po);

    gemm_tf32_kernel<<<ggrid, 256, GM_SMEM>>>((float*)po, (float*)pwp, bp, out);
}